// round 10
// baseline (speedup 1.0000x reference)
#include <cuda_runtime.h>
#include <cuda_fp16.h>
#include <cstdint>

#define MAT 4096
#define SQ  1024
#define HD  128
#define NEG_BIG (-1e30f)

// Scratch (allocation-free rule: device globals)
__device__ __half g_qh [(size_t)MAT * MAT];   // Q fp16, roped+scaled, natural
__device__ __half g_kh [(size_t)MAT * MAT];   // K fp16, roped, natural
__device__ __half g_vh [(size_t)MAT * MAT];   // V fp16, natural
__device__ __half g_vt [(size_t)MAT * MAT];   // V^T fp16  [h*128+d][b*1024+s]
__device__ __half g_att[(size_t)MAT * MAT];   // attn out fp16, k-permuted
__device__ __half g_xh [(size_t)MAT * MAT];   // x fp16, k-permuted
__device__ __half g_wqh[(size_t)MAT * MAT];
__device__ __half g_wkh[(size_t)MAT * MAT];
__device__ __half g_wvh[(size_t)MAT * MAT];
__device__ __half g_woh[(size_t)MAT * MAT];

// ---------------------------------------------------------------------------
__device__ __forceinline__ uint32_t smem_u32(const void* p) {
    uint32_t a;
    asm("{ .reg .u64 t; cvta.to.shared.u64 t, %1; cvt.u32.u64 %0, t; }" : "=r"(a) : "l"(p));
    return a;
}

// fp16 m16n8k16, fp32 accumulate
__device__ __forceinline__ void mma16(float c[4], const uint32_t a[4], const uint32_t b[2]) {
    asm volatile(
        "mma.sync.aligned.m16n8k16.row.col.f32.f16.f16.f32 "
        "{%0,%1,%2,%3},{%4,%5,%6,%7},{%8,%9},{%0,%1,%2,%3};\n"
        : "+f"(c[0]), "+f"(c[1]), "+f"(c[2]), "+f"(c[3])
        : "r"(a[0]), "r"(a[1]), "r"(a[2]), "r"(a[3]), "r"(b[0]), "r"(b[1]));
}

__device__ __forceinline__ void cpa16(uint32_t dst, const void* src) {
    asm volatile("cp.async.cg.shared.global [%0], [%1], 16;" :: "r"(dst), "l"(src));
}
#define CPA_COMMIT() asm volatile("cp.async.commit_group;" ::: "memory")
#define CPA_WAIT(n)  asm volatile("cp.async.wait_group %0;" :: "n"(n) : "memory")

// ---------------------------------------------------------------------------
// fp32 -> fp16 + k-permute pre-pass (GEMM operand layout), 5 matrices.
// Within each 16-block, new position n holds old k = 2*(n>>2) + 8*((n>>1)&1) + (n&1).
// ---------------------------------------------------------------------------
__global__ void conv_h_perm(const float* __restrict__ i0, const float* __restrict__ i1,
                            const float* __restrict__ i2, const float* __restrict__ i3,
                            const float* __restrict__ i4,
                            __half* __restrict__ o0, __half* __restrict__ o1,
                            __half* __restrict__ o2, __half* __restrict__ o3,
                            __half* __restrict__ o4)
{
    const float* in;
    __half* out;
    switch (blockIdx.y) {
        case 0: in = i0; out = o0; break;
        case 1: in = i1; out = o1; break;
        case 2: in = i2; out = o2; break;
        case 3: in = i3; out = o3; break;
        default: in = i4; out = o4; break;
    }
    const int n16 = (MAT * MAT) / 16;
    int i = blockIdx.x * blockDim.x + threadIdx.x;
    const int stride = gridDim.x * blockDim.x;
    for (; i < n16; i += stride) {
        const float4* ip = reinterpret_cast<const float4*>(in) + 4 * (size_t)i;
        float v[16];
        *reinterpret_cast<float4*>(v)      = ip[0];
        *reinterpret_cast<float4*>(v + 4)  = ip[1];
        *reinterpret_cast<float4*>(v + 8)  = ip[2];
        *reinterpret_cast<float4*>(v + 12) = ip[3];
        __half h[16];
#pragma unroll
        for (int n = 0; n < 16; n++) {
            const int k = 2 * (n >> 2) + 8 * ((n >> 1) & 1) + (n & 1);
            h[n] = __float2half_rn(v[k]);
        }
        uint4* op = reinterpret_cast<uint4*>(out + 16 * (size_t)i);
        op[0] = *reinterpret_cast<uint4*>(h);
        op[1] = *reinterpret_cast<uint4*>(h + 8);
    }
}

// ---------------------------------------------------------------------------
// fp16 GEMM: C[m][n] = sum_k A[m][k]*W[n][k]  (4096^3), fp16 + k-permuted in.
// CTA 128x128, BK=64, 4 warps, warp tile 64x64, 2-stage cp.async pipeline.
// Register double-buffered fragments; LDS with folded immediates.
// ---------------------------------------------------------------------------
#define BM 128
#define BN 128
#define BK 64
#define SSTRH 80                           // halves per row (160 B)
#define ABUFH (BM * SSTRH)                 // 10240 halves
#define SPFH  (2 * ABUFH)                  // 20480 halves / stage
#define GS    (2 * SPFH * 2)               // 81920 B
#define NKT   (MAT / BK)                   // 64

__global__ __launch_bounds__(128, 2) void gemm_h(
    const __half* __restrict__ A, const __half* __restrict__ W, void* __restrict__ Cv,
    const float* __restrict__ cosT, const float* __restrict__ sinT,
    int doRope, int f16out, float oscale)
{
    extern __shared__ __half smh[];

    const int tid = threadIdx.x;
    const int bn = blockIdx.x, bm = blockIdx.y;

    const __half* Abase = A + (size_t)(bm * BM) * MAT;
    const __half* Wbase = W + (size_t)(bn * BN) * MAT;
    const uint32_t smb = smem_u32(smh);

    auto issue = [&](int i) {
        const uint32_t as = smb + (uint32_t)(i & 1) * (SPFH * 2);
        const uint32_t bs = as + ABUFH * 2u;
        const int kb = i * BK;
#pragma unroll
        for (int j = 0; j < 8; j++) {
            const int idx = tid + j * 128;
            const int r = idx >> 3, c = idx & 7;
            cpa16(as + (uint32_t)(r * 160 + c * 16), Abase + (size_t)r * MAT + kb + c * 8);
        }
#pragma unroll
        for (int j = 0; j < 8; j++) {
            const int idx = tid + j * 128;
            const int r = idx >> 3, c = idx & 7;
            cpa16(bs + (uint32_t)(r * 160 + c * 16), Wbase + (size_t)r * MAT + kb + c * 8);
        }
        CPA_COMMIT();
    };

    issue(0);
    issue(1);

    const int lane = tid & 31, wrp = tid >> 5;
    const int g = lane >> 2, t = lane & 3;
    const int m0 = (wrp & 1) * 64;            // 2 M-slots
    const int n0 = (wrp >> 1) * 64;           // 2 N-slots

    float acc[4][8][4];
#pragma unroll
    for (int a = 0; a < 4; a++)
#pragma unroll
        for (int b = 0; b < 8; b++)
#pragma unroll
            for (int c = 0; c < 4; c++) acc[a][b][c] = 0.f;

    for (int kt = 0; kt < NKT; kt++) {
        CPA_WAIT(1);
        __syncthreads();

        // element-typed smem pointers; all unrolled offsets are constants
        const uint2* sP = reinterpret_cast<const uint2*>(smh + (size_t)(kt & 1) * SPFH);
        const uint2* aP = sP + (m0 + g) * 20 + t;                 // 20 uint2 per row
        const uint2* bP = sP + (ABUFH / 4) + (n0 + g) * 20 + t;

        uint32_t Af[2][4][4], Bf[2][8][2];
#pragma unroll
        for (int mt = 0; mt < 4; mt++) {
            const uint2 lo = aP[mt * 320];
            const uint2 hi = aP[mt * 320 + 160];
            Af[0][mt][0] = lo.x; Af[0][mt][1] = hi.x; Af[0][mt][2] = lo.y; Af[0][mt][3] = hi.y;
        }
#pragma unroll
        for (int nt = 0; nt < 8; nt++) {
            const uint2 bb = bP[nt * 160];
            Bf[0][nt][0] = bb.x; Bf[0][nt][1] = bb.y;
        }

#pragma unroll
        for (int ks = 0; ks < 4; ks++) {
            const int cur = ks & 1, nxt = cur ^ 1;
            if (ks < 3) {
#pragma unroll
                for (int mt = 0; mt < 4; mt++) {
                    const uint2 lo = aP[mt * 320 + (ks + 1) * 4];
                    const uint2 hi = aP[mt * 320 + 160 + (ks + 1) * 4];
                    Af[nxt][mt][0] = lo.x; Af[nxt][mt][1] = hi.x;
                    Af[nxt][mt][2] = lo.y; Af[nxt][mt][3] = hi.y;
                }
#pragma unroll
                for (int nt = 0; nt < 8; nt++) {
                    const uint2 bb = bP[nt * 160 + (ks + 1) * 4];
                    Bf[nxt][nt][0] = bb.x; Bf[nxt][nt][1] = bb.y;
                }
            }
#pragma unroll
            for (int nt = 0; nt < 8; nt++)
#pragma unroll
                for (int mt = 0; mt < 4; mt++)
                    mma16(acc[mt][nt], Af[cur][mt], Bf[cur][nt]);
        }

        if (kt + 2 < NKT) {
            __syncthreads();
            issue(kt + 2);
        }
    }

    // epilogue (+ fused RoPE); natural layout
#pragma unroll
    for (int mt = 0; mt < 4; mt++) {
        const int gm = bm * BM + m0 + mt * 16 + g;
        const int s0 = gm & (SQ - 1);
#pragma unroll
        for (int nt = 0; nt < 8; nt++) {
            const int cloc = n0 + nt * 8 + 2 * t;       // < 128
            const int gn = bn * BN + cloc;
            float v0 = acc[mt][nt][0], v1 = acc[mt][nt][1];
            float v2 = acc[mt][nt][2], v3 = acc[mt][nt][3];
            if (doRope) {
                const int p = cloc >> 1;
                const float cc0 = cosT[s0 * 64 + p],       ss0 = sinT[s0 * 64 + p];
                const float cc1 = cosT[(s0 + 8) * 64 + p], ss1 = sinT[(s0 + 8) * 64 + p];
                const float w0 = v0 * cc0 - v1 * ss0;
                const float w1 = v0 * ss0 + v1 * cc0;
                const float w2 = v2 * cc1 - v3 * ss1;
                const float w3 = v2 * ss1 + v3 * cc1;
                v0 = w0; v1 = w1; v2 = w2; v3 = w3;
            }
            if (f16out) {
                __half* Ch = (__half*)Cv;
                *reinterpret_cast<__half2*>(Ch + (size_t)gm * MAT + gn) =
                    __floats2half2_rn(v0 * oscale, v1 * oscale);
                *reinterpret_cast<__half2*>(Ch + (size_t)(gm + 8) * MAT + gn) =
                    __floats2half2_rn(v2 * oscale, v3 * oscale);
            } else {
                float* Cf = (float*)Cv;
                *reinterpret_cast<float2*>(Cf + (size_t)gm * MAT + gn)       = make_float2(v0, v1);
                *reinterpret_cast<float2*>(Cf + (size_t)(gm + 8) * MAT + gn) = make_float2(v2, v3);
            }
        }
    }
}

// ---------------------------------------------------------------------------
// Tiled fp16 transpose: out[c][r] = in[r][c]  (4096x4096)
// ---------------------------------------------------------------------------
__global__ __launch_bounds__(256, 4) void transpose_h(
    const __half* __restrict__ in, __half* __restrict__ out)
{
    __shared__ __half ts[64][72];
    const int tid = threadIdx.x;
    const int bx = blockIdx.x, by = blockIdx.y;
#pragma unroll
    for (int i = 0; i < 2; i++) {
        const int idx = tid + i * 256;
        const int r = idx >> 3, c = idx & 7;
        *reinterpret_cast<uint4*>(&ts[r][c * 8]) =
            *reinterpret_cast<const uint4*>(in + (size_t)(by * 64 + r) * MAT + bx * 64 + c * 8);
    }
    __syncthreads();
#pragma unroll
    for (int i = 0; i < 2; i++) {
        const int idx = tid + i * 256;
        const int r = idx >> 3, c = idx & 7;
        __half tmp[8];
#pragma unroll
        for (int j = 0; j < 8; j++) tmp[j] = ts[c * 8 + j][r];
        *reinterpret_cast<uint4*>(out + (size_t)(bx * 64 + r) * MAT + by * 64 + c * 8) =
            *reinterpret_cast<uint4*>(tmp);
    }
}

// ---------------------------------------------------------------------------
// Flash attention, fp16 mma16 (passing R8 kernel, unchanged).
// ---------------------------------------------------------------------------
#define AQSTR 68
#define AVSTR 36
#define ATTN_DW (128 * AQSTR + 64 * AQSTR + 128 * AVSTR + 8 * 16 * AVSTR)
#define ATTN_SMEM (ATTN_DW * 4)

__global__ __launch_bounds__(256, 1) void attn_h(
    const __half* __restrict__ Q, const __half* __restrict__ K,
    const __half* __restrict__ VT, __half* __restrict__ O)
{
    extern __shared__ uint32_t asmem[];
    uint32_t* Qd = asmem;
    uint32_t* Kd = Qd + 128 * AQSTR;
    uint32_t* Vd = Kd + 64 * AQSTR;
    uint32_t* Pd = Vd + 128 * AVSTR;

    const int tid = threadIdx.x;
    const int qt = blockIdx.x, h = blockIdx.y, b = blockIdx.z;
    const int qbase = qt * 128;
    const size_t rowbase = (size_t)b * SQ;

    {
        const __half* qp = Q + (rowbase + qbase) * MAT + h * HD;
#pragma unroll
        for (int i = 0; i < 8; i++) {
            const int idx = tid + i * 256;
            const int row = idx >> 4, c = idx & 15;
            *reinterpret_cast<uint4*>(Qd + row * AQSTR + c * 4) =
                *reinterpret_cast<const uint4*>(qp + (size_t)row * MAT + c * 8);
        }
    }

    const int lane = tid & 31, wrp = tid >> 5;
    const int g = lane >> 2, t = lane & 3;
    const int r0 = wrp * 16;
    uint32_t* Pw = Pd + wrp * 16 * AVSTR;

    float o[16][4];
#pragma unroll
    for (int i = 0; i < 16; i++)
#pragma unroll
        for (int j = 0; j < 4; j++) o[i][j] = 0.f;
    float m0 = NEG_BIG, m1 = NEG_BIG, l0 = 0.f, l1 = 0.f;

    const int nkt = 2 * qt + 2;
    for (int kt = 0; kt < nkt; kt++) {
        __syncthreads();
        {
            const __half* kp = K + (rowbase + kt * 64) * MAT + h * HD;
            const __half* vp = VT + (size_t)(h * HD) * MAT + b * SQ + kt * 64;
#pragma unroll
            for (int i = 0; i < 4; i++) {
                const int idx = tid + i * 256;
                const int row = idx >> 4, c = idx & 15;
                *reinterpret_cast<uint4*>(Kd + row * AQSTR + c * 4) =
                    *reinterpret_cast<const uint4*>(kp + (size_t)row * MAT + c * 8);
            }
#pragma unroll
            for (int i = 0; i < 4; i++) {
                const int idx = tid + i * 256;
                const int row = idx >> 3, c = idx & 7;
                *reinterpret_cast<uint4*>(Vd + row * AVSTR + c * 4) =
                    *reinterpret_cast<const uint4*>(vp + (size_t)row * MAT + c * 8);
            }
        }
        __syncthreads();

        float sfr[8][4];
#pragma unroll
        for (int i = 0; i < 8; i++)
#pragma unroll
            for (int j = 0; j < 4; j++) sfr[i][j] = 0.f;

#pragma unroll
        for (int ks = 0; ks < 8; ks++) {
            const int kd = ks * 8 + t;
            uint32_t af[4] = {
                Qd[(r0 + g) * AQSTR + kd],
                Qd[(r0 + g + 8) * AQSTR + kd],
                Qd[(r0 + g) * AQSTR + kd + 4],
                Qd[(r0 + g + 8) * AQSTR + kd + 4] };
#pragma unroll
            for (int nt = 0; nt < 8; nt++) {
                uint32_t bf[2] = { Kd[(nt * 8 + g) * AQSTR + kd],
                                   Kd[(nt * 8 + g) * AQSTR + kd + 4] };
                mma16(sfr[nt], af, bf);
            }
        }

        if (kt >= 2 * qt) {
            const int qg0 = qbase + r0 + g;
            const int qg1 = qg0 + 8;
#pragma unroll
            for (int nt = 0; nt < 8; nt++) {
                const int kg = kt * 64 + nt * 8 + 2 * t;
                if (kg     > qg0) sfr[nt][0] = NEG_BIG;
                if (kg + 1 > qg0) sfr[nt][1] = NEG_BIG;
                if (kg     > qg1) sfr[nt][2] = NEG_BIG;
                if (kg + 1 > qg1) sfr[nt][3] = NEG_BIG;
            }
        }

        float tm0 = NEG_BIG, tm1 = NEG_BIG;
#pragma unroll
        for (int nt = 0; nt < 8; nt++) {
            tm0 = fmaxf(tm0, fmaxf(sfr[nt][0], sfr[nt][1]));
            tm1 = fmaxf(tm1, fmaxf(sfr[nt][2], sfr[nt][3]));
        }
        tm0 = fmaxf(tm0, __shfl_xor_sync(0xffffffffu, tm0, 1));
        tm0 = fmaxf(tm0, __shfl_xor_sync(0xffffffffu, tm0, 2));
        tm1 = fmaxf(tm1, __shfl_xor_sync(0xffffffffu, tm1, 1));
        tm1 = fmaxf(tm1, __shfl_xor_sync(0xffffffffu, tm1, 2));

        const float mn0 = fmaxf(m0, tm0), mn1 = fmaxf(m1, tm1);
        const float a0 = __expf(m0 - mn0), a1 = __expf(m1 - mn1);
        float ls0 = 0.f, ls1 = 0.f;
#pragma unroll
        for (int nt = 0; nt < 8; nt++) {
            float p0 = __expf(sfr[nt][0] - mn0);
            float p1 = __expf(sfr[nt][1] - mn0);
            float p2 = __expf(sfr[nt][2] - mn1);
            float p3 = __expf(sfr[nt][3] - mn1);
            ls0 += p0 + p1; ls1 += p2 + p3;
            __half2 h01 = __floats2half2_rn(p0, p1);
            __half2 h23 = __floats2half2_rn(p2, p3);
            Pw[g * AVSTR + nt * 4 + t]       = *reinterpret_cast<uint32_t*>(&h01);
            Pw[(g + 8) * AVSTR + nt * 4 + t] = *reinterpret_cast<uint32_t*>(&h23);
        }
        ls0 += __shfl_xor_sync(0xffffffffu, ls0, 1);
        ls0 += __shfl_xor_sync(0xffffffffu, ls0, 2);
        ls1 += __shfl_xor_sync(0xffffffffu, ls1, 1);
        ls1 += __shfl_xor_sync(0xffffffffu, ls1, 2);
        l0 = l0 * a0 + ls0;
        l1 = l1 * a1 + ls1;
        m0 = mn0; m1 = mn1;
#pragma unroll
        for (int nt = 0; nt < 16; nt++) {
            o[nt][0] *= a0; o[nt][1] *= a0; o[nt][2] *= a1; o[nt][3] *= a1;
        }
        __syncwarp();

#pragma unroll
        for (int ks = 0; ks < 4; ks++) {
            const int kd = ks * 8 + t;
            uint32_t af[4] = {
                Pw[g * AVSTR + kd],
                Pw[(g + 8) * AVSTR + kd],
                Pw[g * AVSTR + kd + 4],
                Pw[(g + 8) * AVSTR + kd + 4] };
#pragma unroll
            for (int nt = 0; nt < 16; nt++) {
                uint32_t bf[2] = { Vd[(nt * 8 + g) * AVSTR + kd],
                                   Vd[(nt * 8 + g) * AVSTR + kd + 4] };
                mma16(o[nt], af, bf);
            }
        }
    }

    const float inv0 = 1.f / l0, inv1 = 1.f / l1;
    __half* op  = O + (rowbase + qbase + r0 + g) * MAT + h * HD;
    __half* op2 = op + (size_t)8 * MAT;
#pragma unroll
    for (int nt = 0; nt < 16; nt++) {
        const int pos = (nt >> 1) * 16 + 4 * t + 2 * (nt & 1);
        __half2 h0 = __floats2half2_rn(o[nt][0] * inv0, o[nt][1] * inv0);
        __half2 h1 = __floats2half2_rn(o[nt][2] * inv1, o[nt][3] * inv1);
        *reinterpret_cast<__half2*>(op  + pos) = h0;
        *reinterpret_cast<__half2*>(op2 + pos) = h1;
    }
}

// ---------------------------------------------------------------------------
extern "C" void kernel_launch(void* const* d_in, const int* in_sizes, int n_in,
                              void* d_out, int out_size)
{
    const float* x    = (const float*)d_in[0];
    const float* wq   = (const float*)d_in[1];
    const float* wk   = (const float*)d_in[2];
    const float* wv   = (const float*)d_in[3];
    const float* wo   = (const float*)d_in[4];
    const float* cosT = (const float*)d_in[5];
    const float* sinT = (const float*)d_in[6];
    float* out = (float*)d_out;

    cudaFuncSetAttribute(gemm_h, cudaFuncAttributeMaxDynamicSharedMemorySize, GS);
    cudaFuncSetAttribute(attn_h, cudaFuncAttributeMaxDynamicSharedMemorySize, ATTN_SMEM);

    __half *pq, *pk, *pv, *pvt, *pa, *pxh, *pwq, *pwk, *pwv, *pwo;
    cudaGetSymbolAddress((void**)&pq,  g_qh);
    cudaGetSymbolAddress((void**)&pk,  g_kh);
    cudaGetSymbolAddress((void**)&pv,  g_vh);
    cudaGetSymbolAddress((void**)&pvt, g_vt);
    cudaGetSymbolAddress((void**)&pa,  g_att);
    cudaGetSymbolAddress((void**)&pxh, g_xh);
    cudaGetSymbolAddress((void**)&pwq, g_wqh);
    cudaGetSymbolAddress((void**)&pwk, g_wkh);
    cudaGetSymbolAddress((void**)&pwv, g_wvh);
    cudaGetSymbolAddress((void**)&pwo, g_woh);

    conv_h_perm<<<dim3(1024, 5), 256>>>(x, wq, wk, wv, wo, pxh, pwq, pwk, pwv, pwo);

    dim3 gg(MAT / BN, MAT / BM);   // (32, 32)
    const float qs = 0.08838834764831845f;   // 1/sqrt(128)
    gemm_h<<<gg, 128, GS>>>(pxh, pwq, pq, cosT, sinT, 1, 1, qs);
    gemm_h<<<gg, 128, GS>>>(pxh, pwk, pk, cosT, sinT, 1, 1, 1.0f);
    gemm_h<<<gg, 128, GS>>>(pxh, pwv, pv, cosT, sinT, 0, 1, 1.0f);
    transpose_h<<<dim3(64, 64), 256>>>(pv, pvt);
    attn_h<<<dim3(8, 32, 4), 256, ATTN_SMEM>>>(pq, pk, pvt, pa);
    gemm_h<<<gg, 128, GS>>>(pa, pwo, out, cosT, sinT, 0, 0, 1.0f);
}

// round 12
// speedup vs baseline: 1.0061x; 1.0061x over previous
#include <cuda_runtime.h>
#include <cuda_fp16.h>
#include <cstdint>

#define MAT 4096
#define SQ  1024
#define HD  128
#define NEG_BIG (-1e30f)

// Scratch (allocation-free rule: device globals)
__device__ __half g_qh [(size_t)MAT * MAT];   // Q fp16, roped+scaled, natural
__device__ __half g_kh [(size_t)MAT * MAT];   // K fp16, roped, natural
__device__ __half g_vh [(size_t)MAT * MAT];   // V fp16, natural
__device__ __half g_vt [(size_t)MAT * MAT];   // V^T fp16  [h*128+d][b*1024+s]
__device__ __half g_att[(size_t)MAT * MAT];   // attn out fp16, k-permuted (k16)
__device__ __half g_xh [(size_t)MAT * MAT];   // x fp16, k-permuted (k16)
__device__ __half g_wqh[(size_t)MAT * MAT];
__device__ __half g_wkh[(size_t)MAT * MAT];
__device__ __half g_wvh[(size_t)MAT * MAT];
__device__ __half g_woh[(size_t)MAT * MAT];

// ---------------------------------------------------------------------------
__device__ __forceinline__ uint32_t smem_u32(const void* p) {
    uint32_t a;
    asm("{ .reg .u64 t; cvta.to.shared.u64 t, %1; cvt.u32.u64 %0, t; }" : "=r"(a) : "l"(p));
    return a;
}

// fp16 m16n8k16, fp32 accumulate
__device__ __forceinline__ void mma16(float c[4], const uint32_t a[4], const uint32_t b[2]) {
    asm volatile(
        "mma.sync.aligned.m16n8k16.row.col.f32.f16.f16.f32 "
        "{%0,%1,%2,%3},{%4,%5,%6,%7},{%8,%9},{%0,%1,%2,%3};\n"
        : "+f"(c[0]), "+f"(c[1]), "+f"(c[2]), "+f"(c[3])
        : "r"(a[0]), "r"(a[1]), "r"(a[2]), "r"(a[3]), "r"(b[0]), "r"(b[1]));
}

__device__ __forceinline__ void lds64(uint32_t& x, uint32_t& y, uint32_t addr) {
    asm volatile("ld.shared.v2.b32 {%0,%1}, [%2];" : "=r"(x), "=r"(y) : "r"(addr));
}

__device__ __forceinline__ void cpa16(uint32_t dst, const void* src) {
    asm volatile("cp.async.cg.shared.global [%0], [%1], 16;" :: "r"(dst), "l"(src));
}
#define CPA_COMMIT() asm volatile("cp.async.commit_group;" ::: "memory")
#define CPA_WAIT(n)  asm volatile("cp.async.wait_group %0;" :: "n"(n) : "memory")

// ---------------------------------------------------------------------------
// fp32 -> fp16 + k16-permute pre-pass (GEMM operand layout), 5 matrices.
// Within each 16-block, new position n holds old k = 2*(n>>2) + 8*((n>>1)&1) + (n&1).
// (Proven layout from R8.)
// ---------------------------------------------------------------------------
__global__ void conv_h_perm(const float* __restrict__ i0, const float* __restrict__ i1,
                            const float* __restrict__ i2, const float* __restrict__ i3,
                            const float* __restrict__ i4,
                            __half* __restrict__ o0, __half* __restrict__ o1,
                            __half* __restrict__ o2, __half* __restrict__ o3,
                            __half* __restrict__ o4)
{
    const float* in;
    __half* out;
    switch (blockIdx.y) {
        case 0: in = i0; out = o0; break;
        case 1: in = i1; out = o1; break;
        case 2: in = i2; out = o2; break;
        case 3: in = i3; out = o3; break;
        default: in = i4; out = o4; break;
    }
    const int n16 = (MAT * MAT) / 16;
    int i = blockIdx.x * blockDim.x + threadIdx.x;
    const int stride = gridDim.x * blockDim.x;
    for (; i < n16; i += stride) {
        const float4* ip = reinterpret_cast<const float4*>(in) + 4 * (size_t)i;
        float v[16];
        *reinterpret_cast<float4*>(v)      = ip[0];
        *reinterpret_cast<float4*>(v + 4)  = ip[1];
        *reinterpret_cast<float4*>(v + 8)  = ip[2];
        *reinterpret_cast<float4*>(v + 12) = ip[3];
        __half h[16];
#pragma unroll
        for (int n = 0; n < 16; n++) {
            const int k = 2 * (n >> 2) + 8 * ((n >> 1) & 1) + (n & 1);
            h[n] = __float2half_rn(v[k]);
        }
        uint4* op = reinterpret_cast<uint4*>(out + 16 * (size_t)i);
        op[0] = *reinterpret_cast<uint4*>(h);
        op[1] = *reinterpret_cast<uint4*>(h + 8);
    }
}

// ---------------------------------------------------------------------------
// fp16 GEMM: C[m][n] = sum_k A[m][k]*W[n][k]  (4096^3), fp16 + k16-permuted.
// CTA 128x128, BK=64, 8 warps (warp tile 32x64), 2-stage cp.async pipeline.
// R8 memory layout/fragment path (proven). NEW: fully hoisted cp.async
// addressing — per-ktile issue() is 3 adds + 8 cp.async [reg+imm].
// ---------------------------------------------------------------------------
#define BM 128
#define BN 128
#define BK 64
#define SSTRH 80                           // halves per row (160 B)
#define ABUFH (BM * SSTRH)                 // 10240 halves
#define SPFH  (2 * ABUFH)                  // halves per stage (A+B)
#define GS    (2 * SPFH * 2)               // 81920 B
#define NKT   (MAT / BK)                   // 64

__global__ __launch_bounds__(256, 2) void gemm_h(
    const __half* __restrict__ A, const __half* __restrict__ W, void* __restrict__ Cv,
    const float* __restrict__ cosT, const float* __restrict__ sinT,
    int doRope, int f16out, float oscale)
{
    extern __shared__ __half smh[];
    const uint32_t smb = smem_u32(smh);

    const int tid = threadIdx.x;
    const int bn = blockIdx.x, bm = blockIdx.y;

    // hoisted cp.async addressing
    const int cr = tid >> 3;               // 0..31 (row within 32-row group)
    const int cc = tid & 7;                // 16B chunk 0..7
    const __half* srcA0 = A + (size_t)(bm * BM + cr) * MAT + cc * 8;
    const __half* srcB0 = W + (size_t)(bn * BN + cr) * MAT + cc * 8;
    const uint32_t d0 = smb + (uint32_t)(cr * 160 + cc * 16);

    auto issue = [&](int i) {
        const uint32_t sb = d0 + (uint32_t)(i & 1) * (SPFH * 2);
        const __half* sA = srcA0 + (uint32_t)(i * BK);
        const __half* sB = srcB0 + (uint32_t)(i * BK);
#pragma unroll
        for (int j = 0; j < 4; j++)                       // A: rows cr+32j
            cpa16(sb + (uint32_t)(j * 5120), sA + (size_t)j * (32 * MAT));
#pragma unroll
        for (int j = 0; j < 4; j++)                       // B: rows cr+32j
            cpa16(sb + 20480u + (uint32_t)(j * 5120), sB + (size_t)j * (32 * MAT));
        CPA_COMMIT();
    };

    issue(0);
    issue(1);

    const int lane = tid & 31, wrp = tid >> 5;
    const int g = lane >> 2, t = lane & 3;
    const int m0 = (wrp & 3) * 32;            // 4 M-slots
    const int n0 = (wrp >> 2) * 64;           // 2 N-slots

    // flat smem base addresses (bytes): fragment = base + const (R8 layout)
    const uint32_t aB0 = smb + (uint32_t)(m0 + g) * 160u + (uint32_t)t * 8u;
    const uint32_t bB0 = smb + ABUFH * 2u + (uint32_t)(n0 + g) * 160u + (uint32_t)t * 8u;

    float acc[2][8][4];
#pragma unroll
    for (int a = 0; a < 2; a++)
#pragma unroll
        for (int b = 0; b < 8; b++)
#pragma unroll
            for (int c = 0; c < 4; c++) acc[a][b][c] = 0.f;

    for (int kt = 0; kt < NKT; kt++) {
        CPA_WAIT(1);
        __syncthreads();

        const uint32_t sel = (uint32_t)(kt & 1) * (SPFH * 2);
        const uint32_t aB = aB0 + sel;
        const uint32_t bB = bB0 + sel;

#pragma unroll
        for (int ks = 0; ks < 4; ks++) {
            uint32_t af[2][4];
#pragma unroll
            for (int mt = 0; mt < 2; mt++) {
                lds64(af[mt][0], af[mt][2], aB + mt * 2560 + ks * 32);
                lds64(af[mt][1], af[mt][3], aB + mt * 2560 + 1280 + ks * 32);
            }
#pragma unroll
            for (int nt = 0; nt < 8; nt++) {
                uint32_t bf[2];
                lds64(bf[0], bf[1], bB + nt * 1280 + ks * 32);
                mma16(acc[0][nt], af[0], bf);
                mma16(acc[1][nt], af[1], bf);
            }
        }

        if (kt + 2 < NKT) {
            __syncthreads();
            issue(kt + 2);
        }
    }

    // epilogue (+ fused RoPE); natural layout
#pragma unroll
    for (int mt = 0; mt < 2; mt++) {
        const int gm = bm * BM + m0 + mt * 16 + g;
        const int s0 = gm & (SQ - 1);
#pragma unroll
        for (int nt = 0; nt < 8; nt++) {
            const int cloc = n0 + nt * 8 + 2 * t;       // < 128
            const int gn = bn * BN + cloc;
            float v0 = acc[mt][nt][0], v1 = acc[mt][nt][1];
            float v2 = acc[mt][nt][2], v3 = acc[mt][nt][3];
            if (doRope) {
                const int p = cloc >> 1;
                const float cc0 = cosT[s0 * 64 + p],       ss0 = sinT[s0 * 64 + p];
                const float cc1 = cosT[(s0 + 8) * 64 + p], ss1 = sinT[(s0 + 8) * 64 + p];
                const float w0 = v0 * cc0 - v1 * ss0;
                const float w1 = v0 * ss0 + v1 * cc0;
                const float w2 = v2 * cc1 - v3 * ss1;
                const float w3 = v2 * ss1 + v3 * cc1;
                v0 = w0; v1 = w1; v2 = w2; v3 = w3;
            }
            if (f16out) {
                __half* Ch = (__half*)Cv;
                *reinterpret_cast<__half2*>(Ch + (size_t)gm * MAT + gn) =
                    __floats2half2_rn(v0 * oscale, v1 * oscale);
                *reinterpret_cast<__half2*>(Ch + (size_t)(gm + 8) * MAT + gn) =
                    __floats2half2_rn(v2 * oscale, v3 * oscale);
            } else {
                float* Cf = (float*)Cv;
                *reinterpret_cast<float2*>(Cf + (size_t)gm * MAT + gn)       = make_float2(v0, v1);
                *reinterpret_cast<float2*>(Cf + (size_t)(gm + 8) * MAT + gn) = make_float2(v2, v3);
            }
        }
    }
}

// ---------------------------------------------------------------------------
// Tiled fp16 transpose: out[c][r] = in[r][c]  (4096x4096)
// ---------------------------------------------------------------------------
__global__ __launch_bounds__(256, 4) void transpose_h(
    const __half* __restrict__ in, __half* __restrict__ out)
{
    __shared__ __half ts[64][72];
    const int tid = threadIdx.x;
    const int bx = blockIdx.x, by = blockIdx.y;
#pragma unroll
    for (int i = 0; i < 2; i++) {
        const int idx = tid + i * 256;
        const int r = idx >> 3, c = idx & 7;
        *reinterpret_cast<uint4*>(&ts[r][c * 8]) =
            *reinterpret_cast<const uint4*>(in + (size_t)(by * 64 + r) * MAT + bx * 64 + c * 8);
    }
    __syncthreads();
#pragma unroll
    for (int i = 0; i < 2; i++) {
        const int idx = tid + i * 256;
        const int r = idx >> 3, c = idx & 7;
        __half tmp[8];
#pragma unroll
        for (int j = 0; j < 8; j++) tmp[j] = ts[c * 8 + j][r];
        *reinterpret_cast<uint4*>(out + (size_t)(bx * 64 + r) * MAT + by * 64 + c * 8) =
            *reinterpret_cast<uint4*>(tmp);
    }
}

// ---------------------------------------------------------------------------
// Flash attention, fp16 mma16 (proven R8 kernel, byte-identical).
// ---------------------------------------------------------------------------
#define AQSTR 68
#define AVSTR 36
#define ATTN_DW (128 * AQSTR + 64 * AQSTR + 128 * AVSTR + 8 * 16 * AVSTR)
#define ATTN_SMEM (ATTN_DW * 4)

__global__ __launch_bounds__(256, 1) void attn_h(
    const __half* __restrict__ Q, const __half* __restrict__ K,
    const __half* __restrict__ VT, __half* __restrict__ O)
{
    extern __shared__ uint32_t asmem[];
    uint32_t* Qd = asmem;
    uint32_t* Kd = Qd + 128 * AQSTR;
    uint32_t* Vd = Kd + 64 * AQSTR;
    uint32_t* Pd = Vd + 128 * AVSTR;

    const int tid = threadIdx.x;
    const int qt = blockIdx.x, h = blockIdx.y, b = blockIdx.z;
    const int qbase = qt * 128;
    const size_t rowbase = (size_t)b * SQ;

    {
        const __half* qp = Q + (rowbase + qbase) * MAT + h * HD;
#pragma unroll
        for (int i = 0; i < 8; i++) {
            const int idx = tid + i * 256;
            const int row = idx >> 4, c = idx & 15;
            *reinterpret_cast<uint4*>(Qd + row * AQSTR + c * 4) =
                *reinterpret_cast<const uint4*>(qp + (size_t)row * MAT + c * 8);
        }
    }

    const int lane = tid & 31, wrp = tid >> 5;
    const int g = lane >> 2, t = lane & 3;
    const int r0 = wrp * 16;
    uint32_t* Pw = Pd + wrp * 16 * AVSTR;

    float o[16][4];
#pragma unroll
    for (int i = 0; i < 16; i++)
#pragma unroll
        for (int j = 0; j < 4; j++) o[i][j] = 0.f;
    float m0 = NEG_BIG, m1 = NEG_BIG, l0 = 0.f, l1 = 0.f;

    const int nkt = 2 * qt + 2;
    for (int kt = 0; kt < nkt; kt++) {
        __syncthreads();
        {
            const __half* kp = K + (rowbase + kt * 64) * MAT + h * HD;
            const __half* vp = VT + (size_t)(h * HD) * MAT + b * SQ + kt * 64;
#pragma unroll
            for (int i = 0; i < 4; i++) {
                const int idx = tid + i * 256;
                const int row = idx >> 4, c = idx & 15;
                *reinterpret_cast<uint4*>(Kd + row * AQSTR + c * 4) =
                    *reinterpret_cast<const uint4*>(kp + (size_t)row * MAT + c * 8);
            }
#pragma unroll
            for (int i = 0; i < 4; i++) {
                const int idx = tid + i * 256;
                const int row = idx >> 3, c = idx & 7;
                *reinterpret_cast<uint4*>(Vd + row * AVSTR + c * 4) =
                    *reinterpret_cast<const uint4*>(vp + (size_t)row * MAT + c * 8);
            }
        }
        __syncthreads();

        float sfr[8][4];
#pragma unroll
        for (int i = 0; i < 8; i++)
#pragma unroll
            for (int j = 0; j < 4; j++) sfr[i][j] = 0.f;

#pragma unroll
        for (int ks = 0; ks < 8; ks++) {
            const int kd = ks * 8 + t;
            uint32_t af[4] = {
                Qd[(r0 + g) * AQSTR + kd],
                Qd[(r0 + g + 8) * AQSTR + kd],
                Qd[(r0 + g) * AQSTR + kd + 4],
                Qd[(r0 + g + 8) * AQSTR + kd + 4] };
#pragma unroll
            for (int nt = 0; nt < 8; nt++) {
                uint32_t bf[2] = { Kd[(nt * 8 + g) * AQSTR + kd],
                                   Kd[(nt * 8 + g) * AQSTR + kd + 4] };
                mma16(sfr[nt], af, bf);
            }
        }

        if (kt >= 2 * qt) {
            const int qg0 = qbase + r0 + g;
            const int qg1 = qg0 + 8;
#pragma unroll
            for (int nt = 0; nt < 8; nt++) {
                const int kg = kt * 64 + nt * 8 + 2 * t;
                if (kg     > qg0) sfr[nt][0] = NEG_BIG;
                if (kg + 1 > qg0) sfr[nt][1] = NEG_BIG;
                if (kg     > qg1) sfr[nt][2] = NEG_BIG;
                if (kg + 1 > qg1) sfr[nt][3] = NEG_BIG;
            }
        }

        float tm0 = NEG_BIG, tm1 = NEG_BIG;
#pragma unroll
        for (int nt = 0; nt < 8; nt++) {
            tm0 = fmaxf(tm0, fmaxf(sfr[nt][0], sfr[nt][1]));
            tm1 = fmaxf(tm1, fmaxf(sfr[nt][2], sfr[nt][3]));
        }
        tm0 = fmaxf(tm0, __shfl_xor_sync(0xffffffffu, tm0, 1));
        tm0 = fmaxf(tm0, __shfl_xor_sync(0xffffffffu, tm0, 2));
        tm1 = fmaxf(tm1, __shfl_xor_sync(0xffffffffu, tm1, 1));
        tm1 = fmaxf(tm1, __shfl_xor_sync(0xffffffffu, tm1, 2));

        const float mn0 = fmaxf(m0, tm0), mn1 = fmaxf(m1, tm1);
        const float a0 = __expf(m0 - mn0), a1 = __expf(m1 - mn1);
        float ls0 = 0.f, ls1 = 0.f;
#pragma unroll
        for (int nt = 0; nt < 8; nt++) {
            float p0 = __expf(sfr[nt][0] - mn0);
            float p1 = __expf(sfr[nt][1] - mn0);
            float p2 = __expf(sfr[nt][2] - mn1);
            float p3 = __expf(sfr[nt][3] - mn1);
            ls0 += p0 + p1; ls1 += p2 + p3;
            __half2 h01 = __floats2half2_rn(p0, p1);
            __half2 h23 = __floats2half2_rn(p2, p3);
            Pw[g * AVSTR + nt * 4 + t]       = *reinterpret_cast<uint32_t*>(&h01);
            Pw[(g + 8) * AVSTR + nt * 4 + t] = *reinterpret_cast<uint32_t*>(&h23);
        }
        ls0 += __shfl_xor_sync(0xffffffffu, ls0, 1);
        ls0 += __shfl_xor_sync(0xffffffffu, ls0, 2);
        ls1 += __shfl_xor_sync(0xffffffffu, ls1, 1);
        ls1 += __shfl_xor_sync(0xffffffffu, ls1, 2);
        l0 = l0 * a0 + ls0;
        l1 = l1 * a1 + ls1;
        m0 = mn0; m1 = mn1;
#pragma unroll
        for (int nt = 0; nt < 16; nt++) {
            o[nt][0] *= a0; o[nt][1] *= a0; o[nt][2] *= a1; o[nt][3] *= a1;
        }
        __syncwarp();

#pragma unroll
        for (int ks = 0; ks < 4; ks++) {
            const int kd = ks * 8 + t;
            uint32_t af[4] = {
                Pw[g * AVSTR + kd],
                Pw[(g + 8) * AVSTR + kd],
                Pw[g * AVSTR + kd + 4],
                Pw[(g + 8) * AVSTR + kd + 4] };
#pragma unroll
            for (int nt = 0; nt < 16; nt++) {
                uint32_t bf[2] = { Vd[(nt * 8 + g) * AVSTR + kd],
                                   Vd[(nt * 8 + g) * AVSTR + kd + 4] };
                mma16(o[nt], af, bf);
            }
        }
    }

    // fp16 + k16-permuted output store (Wo GEMM operand layout), proven in R8:
    // col pair (nt, 2t) -> position (nt>>1)*16 + 4t + 2*(nt&1)
    const float inv0 = 1.f / l0, inv1 = 1.f / l1;
    __half* op  = O + (rowbase + qbase + r0 + g) * MAT + h * HD;
    __half* op2 = op + (size_t)8 * MAT;
#pragma unroll
    for (int nt = 0; nt < 16; nt++) {
        const int pos = (nt >> 1) * 16 + 4 * t + 2 * (nt & 1);
        __half2 h0 = __floats2half2_rn(o[nt][0] * inv0, o[nt][1] * inv0);
        __half2 h1 = __floats2half2_rn(o[nt][2] * inv1, o[nt][3] * inv1);
        *reinterpret_cast<__half2*>(op  + pos) = h0;
        *reinterpret_cast<__half2*>(op2 + pos) = h1;
    }
}

// ---------------------------------------------------------------------------
extern "C" void kernel_launch(void* const* d_in, const int* in_sizes, int n_in,
                              void* d_out, int out_size)
{
    const float* x    = (const float*)d_in[0];
    const float* wq   = (const float*)d_in[1];
    const float* wk   = (const float*)d_in[2];
    const float* wv   = (const float*)d_in[3];
    const float* wo   = (const float*)d_in[4];
    const float* cosT = (const float*)d_in[5];
    const float* sinT = (const float*)d_in[6];
    float* out = (float*)d_out;

    cudaFuncSetAttribute(gemm_h, cudaFuncAttributeMaxDynamicSharedMemorySize, GS);
    cudaFuncSetAttribute(attn_h, cudaFuncAttributeMaxDynamicSharedMemorySize, ATTN_SMEM);

    __half *pq, *pk, *pv, *pvt, *pa, *pxh, *pwq, *pwk, *pwv, *pwo;
    cudaGetSymbolAddress((void**)&pq,  g_qh);
    cudaGetSymbolAddress((void**)&pk,  g_kh);
    cudaGetSymbolAddress((void**)&pv,  g_vh);
    cudaGetSymbolAddress((void**)&pvt, g_vt);
    cudaGetSymbolAddress((void**)&pa,  g_att);
    cudaGetSymbolAddress((void**)&pxh, g_xh);
    cudaGetSymbolAddress((void**)&pwq, g_wqh);
    cudaGetSymbolAddress((void**)&pwk, g_wkh);
    cudaGetSymbolAddress((void**)&pwv, g_wvh);
    cudaGetSymbolAddress((void**)&pwo, g_woh);

    conv_h_perm<<<dim3(1024, 5), 256>>>(x, wq, wk, wv, wo, pxh, pwq, pwk, pwv, pwo);

    dim3 gg(MAT / BN, MAT / BM);   // (32, 32)
    const float qs = 0.08838834764831845f;   // 1/sqrt(128)
    gemm_h<<<gg, 256, GS>>>(pxh, pwq, pq, cosT, sinT, 1, 1, qs);
    gemm_h<<<gg, 256, GS>>>(pxh, pwk, pk, cosT, sinT, 1, 1, 1.0f);
    gemm_h<<<gg, 256, GS>>>(pxh, pwv, pv, cosT, sinT, 0, 1, 1.0f);
    transpose_h<<<dim3(64, 64), 256>>>(pv, pvt);
    attn_h<<<dim3(8, 32, 4), 256, ATTN_SMEM>>>(pq, pk, pvt, pa);
    gemm_h<<<gg, 256, GS>>>(pa, pwo, out, cosT, sinT, 0, 0, 1.0f);
}

// round 14
// speedup vs baseline: 1.0390x; 1.0327x over previous
#include <cuda_runtime.h>
#include <cuda_fp16.h>
#include <cstdint>

#define MAT 4096
#define SQ  1024
#define HD  128
#define NEG_BIG (-1e30f)

// Scratch (allocation-free rule: device globals)
__device__ __half g_qh [(size_t)MAT * MAT];   // Q fp16, roped+scaled, natural
__device__ __half g_kh [(size_t)MAT * MAT];   // K fp16, roped, natural
__device__ __half g_vh [(size_t)MAT * MAT];   // V fp16, natural
__device__ __half g_vt [(size_t)MAT * MAT];   // V^T fp16  [h*128+d][b*1024+s]
__device__ __half g_att[(size_t)MAT * MAT];   // attn out fp16, k-permuted (k16)
__device__ __half g_xh [(size_t)MAT * MAT];   // x fp16, k-permuted (k16)
__device__ __half g_wqh[(size_t)MAT * MAT];
__device__ __half g_wkh[(size_t)MAT * MAT];
__device__ __half g_wvh[(size_t)MAT * MAT];
__device__ __half g_woh[(size_t)MAT * MAT];

// ---------------------------------------------------------------------------
__device__ __forceinline__ uint32_t smem_u32(const void* p) {
    uint32_t a;
    asm("{ .reg .u64 t; cvta.to.shared.u64 t, %1; cvt.u32.u64 %0, t; }" : "=r"(a) : "l"(p));
    return a;
}

// fp16 m16n8k16, fp32 accumulate
__device__ __forceinline__ void mma16(float c[4], const uint32_t a[4], const uint32_t b[2]) {
    asm volatile(
        "mma.sync.aligned.m16n8k16.row.col.f32.f16.f16.f32 "
        "{%0,%1,%2,%3},{%4,%5,%6,%7},{%8,%9},{%0,%1,%2,%3};\n"
        : "+f"(c[0]), "+f"(c[1]), "+f"(c[2]), "+f"(c[3])
        : "r"(a[0]), "r"(a[1]), "r"(a[2]), "r"(a[3]), "r"(b[0]), "r"(b[1]));
}

__device__ __forceinline__ void lds64(uint32_t& x, uint32_t& y, uint32_t addr) {
    asm volatile("ld.shared.v2.b32 {%0,%1}, [%2];" : "=r"(x), "=r"(y) : "r"(addr));
}

__device__ __forceinline__ void cpa16(uint32_t dst, const void* src) {
    asm volatile("cp.async.cg.shared.global [%0], [%1], 16;" :: "r"(dst), "l"(src));
}
#define CPA_COMMIT() asm volatile("cp.async.commit_group;" ::: "memory")
#define CPA_WAIT(n)  asm volatile("cp.async.wait_group %0;" :: "n"(n) : "memory")

// ---------------------------------------------------------------------------
// fp32 -> fp16 + k16-permute pre-pass (GEMM operand layout), 5 matrices.
// Within each 16-block, new position n holds old k = 2*(n>>2) + 8*((n>>1)&1) + (n&1).
// ---------------------------------------------------------------------------
__global__ void conv_h_perm(const float* __restrict__ i0, const float* __restrict__ i1,
                            const float* __restrict__ i2, const float* __restrict__ i3,
                            const float* __restrict__ i4,
                            __half* __restrict__ o0, __half* __restrict__ o1,
                            __half* __restrict__ o2, __half* __restrict__ o3,
                            __half* __restrict__ o4)
{
    const float* in;
    __half* out;
    switch (blockIdx.y) {
        case 0: in = i0; out = o0; break;
        case 1: in = i1; out = o1; break;
        case 2: in = i2; out = o2; break;
        case 3: in = i3; out = o3; break;
        default: in = i4; out = o4; break;
    }
    const int n16 = (MAT * MAT) / 16;
    int i = blockIdx.x * blockDim.x + threadIdx.x;
    const int stride = gridDim.x * blockDim.x;
    for (; i < n16; i += stride) {
        const float4* ip = reinterpret_cast<const float4*>(in) + 4 * (size_t)i;
        float v[16];
        *reinterpret_cast<float4*>(v)      = ip[0];
        *reinterpret_cast<float4*>(v + 4)  = ip[1];
        *reinterpret_cast<float4*>(v + 8)  = ip[2];
        *reinterpret_cast<float4*>(v + 12) = ip[3];
        __half h[16];
#pragma unroll
        for (int n = 0; n < 16; n++) {
            const int k = 2 * (n >> 2) + 8 * ((n >> 1) & 1) + (n & 1);
            h[n] = __float2half_rn(v[k]);
        }
        uint4* op = reinterpret_cast<uint4*>(out + 16 * (size_t)i);
        op[0] = *reinterpret_cast<uint4*>(h);
        op[1] = *reinterpret_cast<uint4*>(h + 8);
    }
}

// ---------------------------------------------------------------------------
// fp16 GEMM, persistent tiles: 304 CTAs grid-stride over 32x32 output tiles.
// CTA tile 128x128, BK=64, 8 warps (warp tile 32x64), 2-stage cp.async.
// Proven R8 smem layout (k16 perm, 160B rows, LDS.64 fragments).
// ---------------------------------------------------------------------------
#define BM 128
#define BN 128
#define BK 64
#define SSTRH 80                           // halves per row (160 B)
#define ABUFH (BM * SSTRH)                 // 10240 halves
#define SPFH  (2 * ABUFH)                  // halves per stage (A+B)
#define GS    (2 * SPFH * 2)               // 81920 B
#define NKT   (MAT / BK)                   // 64
#define NTILES 1024
#define GEMM_CTAS 304

__global__ __launch_bounds__(256, 2) void gemm_h(
    const __half* __restrict__ A, const __half* __restrict__ W, void* __restrict__ Cv,
    const float* __restrict__ cosT, const float* __restrict__ sinT,
    int doRope, int f16out, float oscale)
{
    extern __shared__ __half smh[];
    const uint32_t smb = smem_u32(smh);

    const int tid = threadIdx.x;
    const int cr = tid >> 3;               // 0..31 (row within 32-row group)
    const int cc = tid & 7;                // 16B chunk 0..7
    const uint32_t d0 = smb + (uint32_t)(cr * 160 + cc * 16);

    const int lane = tid & 31, wrp = tid >> 5;
    const int g = lane >> 2, t = lane & 3;
    const int m0 = (wrp & 3) * 32;            // 4 M-slots
    const int n0 = (wrp >> 2) * 64;           // 2 N-slots
    const uint32_t aB0 = smb + (uint32_t)(m0 + g) * 160u + (uint32_t)t * 8u;
    const uint32_t bB0 = smb + ABUFH * 2u + (uint32_t)(n0 + g) * 160u + (uint32_t)t * 8u;

    const __half* srcA0;
    const __half* srcB0;

    auto issue = [&](int i) {
        const uint32_t sb = d0 + (uint32_t)(i & 1) * (SPFH * 2);
        const __half* sA = srcA0 + (uint32_t)(i * BK);
        const __half* sB = srcB0 + (uint32_t)(i * BK);
#pragma unroll
        for (int j = 0; j < 4; j++)
            cpa16(sb + (uint32_t)(j * 5120), sA + (size_t)j * (32 * MAT));
#pragma unroll
        for (int j = 0; j < 4; j++)
            cpa16(sb + 20480u + (uint32_t)(j * 5120), sB + (size_t)j * (32 * MAT));
        CPA_COMMIT();
    };

    for (int tile = blockIdx.x; tile < NTILES; tile += gridDim.x) {
        const int bm = tile >> 5, bn = tile & 31;
        srcA0 = A + (size_t)(bm * BM + cr) * MAT + cc * 8;
        srcB0 = W + (size_t)(bn * BN + cr) * MAT + cc * 8;

        if (tile != blockIdx.x) __syncthreads();   // smem reads of prev tile done
        issue(0);
        issue(1);

        float acc[2][8][4];
#pragma unroll
        for (int a = 0; a < 2; a++)
#pragma unroll
            for (int b = 0; b < 8; b++)
#pragma unroll
                for (int c = 0; c < 4; c++) acc[a][b][c] = 0.f;

        for (int kt = 0; kt < NKT; kt++) {
            if (kt + 1 < NKT) { CPA_WAIT(1); } else { CPA_WAIT(0); }
            __syncthreads();

            const uint32_t sel = (uint32_t)(kt & 1) * (SPFH * 2);
            const uint32_t aB = aB0 + sel;
            const uint32_t bB = bB0 + sel;

#pragma unroll
            for (int ks = 0; ks < 4; ks++) {
                uint32_t af[2][4];
#pragma unroll
                for (int mt = 0; mt < 2; mt++) {
                    lds64(af[mt][0], af[mt][2], aB + mt * 2560 + ks * 32);
                    lds64(af[mt][1], af[mt][3], aB + mt * 2560 + 1280 + ks * 32);
                }
#pragma unroll
                for (int nt = 0; nt < 8; nt++) {
                    uint32_t bf[2];
                    lds64(bf[0], bf[1], bB + nt * 1280 + ks * 32);
                    mma16(acc[0][nt], af[0], bf);
                    mma16(acc[1][nt], af[1], bf);
                }
            }

            if (kt + 2 < NKT) {
                __syncthreads();
                issue(kt + 2);
            }
        }

        // epilogue (+ fused RoPE); natural layout
#pragma unroll
        for (int mt = 0; mt < 2; mt++) {
            const int gm = bm * BM + m0 + mt * 16 + g;
            const int s0 = gm & (SQ - 1);
#pragma unroll
            for (int nt = 0; nt < 8; nt++) {
                const int cloc = n0 + nt * 8 + 2 * t;       // < 128
                const int gn = bn * BN + cloc;
                float v0 = acc[mt][nt][0], v1 = acc[mt][nt][1];
                float v2 = acc[mt][nt][2], v3 = acc[mt][nt][3];
                if (doRope) {
                    const int p = cloc >> 1;
                    const float cc0 = cosT[s0 * 64 + p],       ss0 = sinT[s0 * 64 + p];
                    const float cc1 = cosT[(s0 + 8) * 64 + p], ss1 = sinT[(s0 + 8) * 64 + p];
                    const float w0 = v0 * cc0 - v1 * ss0;
                    const float w1 = v0 * ss0 + v1 * cc0;
                    const float w2 = v2 * cc1 - v3 * ss1;
                    const float w3 = v2 * ss1 + v3 * cc1;
                    v0 = w0; v1 = w1; v2 = w2; v3 = w3;
                }
                if (f16out) {
                    __half* Ch = (__half*)Cv;
                    *reinterpret_cast<__half2*>(Ch + (size_t)gm * MAT + gn) =
                        __floats2half2_rn(v0 * oscale, v1 * oscale);
                    *reinterpret_cast<__half2*>(Ch + (size_t)(gm + 8) * MAT + gn) =
                        __floats2half2_rn(v2 * oscale, v3 * oscale);
                } else {
                    float* Cf = (float*)Cv;
                    *reinterpret_cast<float2*>(Cf + (size_t)gm * MAT + gn)       = make_float2(v0, v1);
                    *reinterpret_cast<float2*>(Cf + (size_t)(gm + 8) * MAT + gn) = make_float2(v2, v3);
                }
            }
        }
    }
}

// ---------------------------------------------------------------------------
// Tiled fp16 transpose: out[c][r] = in[r][c]  (4096x4096)
// ---------------------------------------------------------------------------
__global__ __launch_bounds__(256, 4) void transpose_h(
    const __half* __restrict__ in, __half* __restrict__ out)
{
    __shared__ __half ts[64][72];
    const int tid = threadIdx.x;
    const int bx = blockIdx.x, by = blockIdx.y;
#pragma unroll
    for (int i = 0; i < 2; i++) {
        const int idx = tid + i * 256;
        const int r = idx >> 3, c = idx & 7;
        *reinterpret_cast<uint4*>(&ts[r][c * 8]) =
            *reinterpret_cast<const uint4*>(in + (size_t)(by * 64 + r) * MAT + bx * 64 + c * 8);
    }
    __syncthreads();
#pragma unroll
    for (int i = 0; i < 2; i++) {
        const int idx = tid + i * 256;
        const int r = idx >> 3, c = idx & 7;
        __half tmp[8];
#pragma unroll
        for (int j = 0; j < 8; j++) tmp[j] = ts[c * 8 + j][r];
        *reinterpret_cast<uint4*>(out + (size_t)(bx * 64 + r) * MAT + by * 64 + c * 8) =
            *reinterpret_cast<uint4*>(tmp);
    }
}

// ---------------------------------------------------------------------------
// Flash attention, fp16 mma16 (proven R8 kernel; occupancy 2/SM).
// ---------------------------------------------------------------------------
#define AQSTR 68
#define AVSTR 36
#define ATTN_DW (128 * AQSTR + 64 * AQSTR + 128 * AVSTR + 8 * 16 * AVSTR)
#define ATTN_SMEM (ATTN_DW * 4)

__global__ __launch_bounds__(256, 2) void attn_h(
    const __half* __restrict__ Q, const __half* __restrict__ K,
    const __half* __restrict__ VT, __half* __restrict__ O)
{
    extern __shared__ uint32_t asmem[];
    uint32_t* Qd = asmem;
    uint32_t* Kd = Qd + 128 * AQSTR;
    uint32_t* Vd = Kd + 64 * AQSTR;
    uint32_t* Pd = Vd + 128 * AVSTR;

    const int tid = threadIdx.x;
    const int qt = blockIdx.x, h = blockIdx.y, b = blockIdx.z;
    const int qbase = qt * 128;
    const size_t rowbase = (size_t)b * SQ;

    {
        const __half* qp = Q + (rowbase + qbase) * MAT + h * HD;
#pragma unroll
        for (int i = 0; i < 8; i++) {
            const int idx = tid + i * 256;
            const int row = idx >> 4, c = idx & 15;
            *reinterpret_cast<uint4*>(Qd + row * AQSTR + c * 4) =
                *reinterpret_cast<const uint4*>(qp + (size_t)row * MAT + c * 8);
        }
    }

    const int lane = tid & 31, wrp = tid >> 5;
    const int g = lane >> 2, t = lane & 3;
    const int r0 = wrp * 16;
    uint32_t* Pw = Pd + wrp * 16 * AVSTR;

    float o[16][4];
#pragma unroll
    for (int i = 0; i < 16; i++)
#pragma unroll
        for (int j = 0; j < 4; j++) o[i][j] = 0.f;
    float m0 = NEG_BIG, m1 = NEG_BIG, l0 = 0.f, l1 = 0.f;

    const int nkt = 2 * qt + 2;
    for (int kt = 0; kt < nkt; kt++) {
        __syncthreads();
        {
            const __half* kp = K + (rowbase + kt * 64) * MAT + h * HD;
            const __half* vp = VT + (size_t)(h * HD) * MAT + b * SQ + kt * 64;
#pragma unroll
            for (int i = 0; i < 4; i++) {
                const int idx = tid + i * 256;
                const int row = idx >> 4, c = idx & 15;
                *reinterpret_cast<uint4*>(Kd + row * AQSTR + c * 4) =
                    *reinterpret_cast<const uint4*>(kp + (size_t)row * MAT + c * 8);
            }
#pragma unroll
            for (int i = 0; i < 4; i++) {
                const int idx = tid + i * 256;
                const int row = idx >> 3, c = idx & 7;
                *reinterpret_cast<uint4*>(Vd + row * AVSTR + c * 4) =
                    *reinterpret_cast<const uint4*>(vp + (size_t)row * MAT + c * 8);
            }
        }
        __syncthreads();

        float sfr[8][4];
#pragma unroll
        for (int i = 0; i < 8; i++)
#pragma unroll
            for (int j = 0; j < 4; j++) sfr[i][j] = 0.f;

#pragma unroll
        for (int ks = 0; ks < 8; ks++) {
            const int kd = ks * 8 + t;
            uint32_t af[4] = {
                Qd[(r0 + g) * AQSTR + kd],
                Qd[(r0 + g + 8) * AQSTR + kd],
                Qd[(r0 + g) * AQSTR + kd + 4],
                Qd[(r0 + g + 8) * AQSTR + kd + 4] };
#pragma unroll
            for (int nt = 0; nt < 8; nt++) {
                uint32_t bf[2] = { Kd[(nt * 8 + g) * AQSTR + kd],
                                   Kd[(nt * 8 + g) * AQSTR + kd + 4] };
                mma16(sfr[nt], af, bf);
            }
        }

        if (kt >= 2 * qt) {
            const int qg0 = qbase + r0 + g;
            const int qg1 = qg0 + 8;
#pragma unroll
            for (int nt = 0; nt < 8; nt++) {
                const int kg = kt * 64 + nt * 8 + 2 * t;
                if (kg     > qg0) sfr[nt][0] = NEG_BIG;
                if (kg + 1 > qg0) sfr[nt][1] = NEG_BIG;
                if (kg     > qg1) sfr[nt][2] = NEG_BIG;
                if (kg + 1 > qg1) sfr[nt][3] = NEG_BIG;
            }
        }

        float tm0 = NEG_BIG, tm1 = NEG_BIG;
#pragma unroll
        for (int nt = 0; nt < 8; nt++) {
            tm0 = fmaxf(tm0, fmaxf(sfr[nt][0], sfr[nt][1]));
            tm1 = fmaxf(tm1, fmaxf(sfr[nt][2], sfr[nt][3]));
        }
        tm0 = fmaxf(tm0, __shfl_xor_sync(0xffffffffu, tm0, 1));
        tm0 = fmaxf(tm0, __shfl_xor_sync(0xffffffffu, tm0, 2));
        tm1 = fmaxf(tm1, __shfl_xor_sync(0xffffffffu, tm1, 1));
        tm1 = fmaxf(tm1, __shfl_xor_sync(0xffffffffu, tm1, 2));

        const float mn0 = fmaxf(m0, tm0), mn1 = fmaxf(m1, tm1);
        const float a0 = __expf(m0 - mn0), a1 = __expf(m1 - mn1);
        float ls0 = 0.f, ls1 = 0.f;
#pragma unroll
        for (int nt = 0; nt < 8; nt++) {
            float p0 = __expf(sfr[nt][0] - mn0);
            float p1 = __expf(sfr[nt][1] - mn0);
            float p2 = __expf(sfr[nt][2] - mn1);
            float p3 = __expf(sfr[nt][3] - mn1);
            ls0 += p0 + p1; ls1 += p2 + p3;
            __half2 h01 = __floats2half2_rn(p0, p1);
            __half2 h23 = __floats2half2_rn(p2, p3);
            Pw[g * AVSTR + nt * 4 + t]       = *reinterpret_cast<uint32_t*>(&h01);
            Pw[(g + 8) * AVSTR + nt * 4 + t] = *reinterpret_cast<uint32_t*>(&h23);
        }
        ls0 += __shfl_xor_sync(0xffffffffu, ls0, 1);
        ls0 += __shfl_xor_sync(0xffffffffu, ls0, 2);
        ls1 += __shfl_xor_sync(0xffffffffu, ls1, 1);
        ls1 += __shfl_xor_sync(0xffffffffu, ls1, 2);
        l0 = l0 * a0 + ls0;
        l1 = l1 * a1 + ls1;
        m0 = mn0; m1 = mn1;
#pragma unroll
        for (int nt = 0; nt < 16; nt++) {
            o[nt][0] *= a0; o[nt][1] *= a0; o[nt][2] *= a1; o[nt][3] *= a1;
        }
        __syncwarp();

#pragma unroll
        for (int ks = 0; ks < 4; ks++) {
            const int kd = ks * 8 + t;
            uint32_t af[4] = {
                Pw[g * AVSTR + kd],
                Pw[(g + 8) * AVSTR + kd],
                Pw[g * AVSTR + kd + 4],
                Pw[(g + 8) * AVSTR + kd + 4] };
#pragma unroll
            for (int nt = 0; nt < 16; nt++) {
                uint32_t bf[2] = { Vd[(nt * 8 + g) * AVSTR + kd],
                                   Vd[(nt * 8 + g) * AVSTR + kd + 4] };
                mma16(o[nt], af, bf);
            }
        }
    }

    // fp16 + k16-permuted output store (Wo GEMM operand layout):
    // col pair (nt, 2t) -> position (nt>>1)*16 + 4t + 2*(nt&1)
    const float inv0 = 1.f / l0, inv1 = 1.f / l1;
    __half* op  = O + (rowbase + qbase + r0 + g) * MAT + h * HD;
    __half* op2 = op + (size_t)8 * MAT;
#pragma unroll
    for (int nt = 0; nt < 16; nt++) {
        const int pos = (nt >> 1) * 16 + 4 * t + 2 * (nt & 1);
        __half2 h0 = __floats2half2_rn(o[nt][0] * inv0, o[nt][1] * inv0);
        __half2 h1 = __floats2half2_rn(o[nt][2] * inv1, o[nt][3] * inv1);
        *reinterpret_cast<__half2*>(op  + pos) = h0;
        *reinterpret_cast<__half2*>(op2 + pos) = h1;
    }
}

// ---------------------------------------------------------------------------
extern "C" void kernel_launch(void* const* d_in, const int* in_sizes, int n_in,
                              void* d_out, int out_size)
{
    const float* x    = (const float*)d_in[0];
    const float* wq   = (const float*)d_in[1];
    const float* wk   = (const float*)d_in[2];
    const float* wv   = (const float*)d_in[3];
    const float* wo   = (const float*)d_in[4];
    const float* cosT = (const float*)d_in[5];
    const float* sinT = (const float*)d_in[6];
    float* out = (float*)d_out;

    cudaFuncSetAttribute(gemm_h, cudaFuncAttributeMaxDynamicSharedMemorySize, GS);
    cudaFuncSetAttribute(attn_h, cudaFuncAttributeMaxDynamicSharedMemorySize, ATTN_SMEM);

    __half *pq, *pk, *pv, *pvt, *pa, *pxh, *pwq, *pwk, *pwv, *pwo;
    cudaGetSymbolAddress((void**)&pq,  g_qh);
    cudaGetSymbolAddress((void**)&pk,  g_kh);
    cudaGetSymbolAddress((void**)&pv,  g_vh);
    cudaGetSymbolAddress((void**)&pvt, g_vt);
    cudaGetSymbolAddress((void**)&pa,  g_att);
    cudaGetSymbolAddress((void**)&pxh, g_xh);
    cudaGetSymbolAddress((void**)&pwq, g_wqh);
    cudaGetSymbolAddress((void**)&pwk, g_wkh);
    cudaGetSymbolAddress((void**)&pwv, g_wvh);
    cudaGetSymbolAddress((void**)&pwo, g_woh);

    conv_h_perm<<<dim3(1024, 5), 256>>>(x, wq, wk, wv, wo, pxh, pwq, pwk, pwv, pwo);

    const float qs = 0.08838834764831845f;   // 1/sqrt(128)
    gemm_h<<<GEMM_CTAS, 256, GS>>>(pxh, pwq, pq, cosT, sinT, 1, 1, qs);
    gemm_h<<<GEMM_CTAS, 256, GS>>>(pxh, pwk, pk, cosT, sinT, 1, 1, 1.0f);
    gemm_h<<<GEMM_CTAS, 256, GS>>>(pxh, pwv, pv, cosT, sinT, 0, 1, 1.0f);
    transpose_h<<<dim3(64, 64), 256>>>(pv, pvt);
    attn_h<<<dim3(8, 32, 4), 256, ATTN_SMEM>>>(pq, pk, pvt, pa);
    gemm_h<<<GEMM_CTAS, 256, GS>>>(pa, pwo, out, cosT, sinT, 0, 0, 1.0f);
}